// round 13
// baseline (speedup 1.0000x reference)
#include <cuda_runtime.h>

// AverageSpanExtractor: out[b,n,:] = mean(seq[b, start:end, :]) * mask[b,n]
// seq: [B,S,D] f32; spans: [B,N,2] i32; mask: [B,N] i32; out: [B,N,D] f32.
//
// Bucketed-locality kernel: CTA per (batch, 16-row start bucket), 1024 CTAs
// x 128 threads (the execution shape that ran best). The CTA filters the
// batch's span list (8 coalesced rounds) for spans starting in its bucket
// (~8 spans), then reduces them serially with the proven per-span body.
// Those spans' rows live in a <=36-row (72KB) window << L1D, so after the
// first span the gather hits L1 instead of L2 -- cutting the L2 traffic
// that capped every flat scheme at ~15us.

#define MAX_W    20
#define DIM      512
#define D4       (DIM / 4)
#define BW       16          // bucket width (rows)
#define LIST_CAP 96          // Poisson(8) spans/bucket; 96 is unreachable

__global__ __launch_bounds__(128, 8)
void avg_span_kernel(const float* __restrict__ seq,
                     const int* __restrict__ spans,
                     const int* __restrict__ mask,
                     float* __restrict__ out,
                     int S, int N)
{
    __shared__ int4 list[LIST_CAP];      // (n, start, width, mask)
    __shared__ int  cnt;

    const int bucket = blockIdx.x;
    const int b      = blockIdx.y;
    const int t      = threadIdx.x;      // 0..127, owns float4 column t

    if (t == 0) cnt = 0;
    __syncthreads();

    const int lo = bucket * BW;
    const int hi = lo + BW;

    // ---- filter: spans of batch b starting in [lo, hi) ----
    const int2* sp2 = (const int2*)spans + b * N;
    for (int n = t; n < N; n += 128) {
        const int2 se = sp2[n];
        if (se.x >= lo && se.x < hi) {
            int w = se.y - se.x;
            w = (w < MAX_W) ? w : MAX_W;     // reference's static clamp
            w = (w > 0) ? w : 1;
            const int i = atomicAdd(&cnt, 1);
            if (i < LIST_CAP) {
                list[i] = make_int4(n, se.x, w, mask[b * N + n]);
            } else {
                // statistically unreachable overflow: reduce solo, correct
                const float scale = (float)mask[b * N + n] / (float)w;
                const float* g = seq + ((long long)b * S + se.x) * DIM;
                float* o = out + ((long long)(b * N + n)) * DIM;
                for (int d = 0; d < DIM; ++d) {
                    float a = 0.f;
                    for (int r = 0; r < w; ++r) a += g[r * DIM + d];
                    o[d] = a * scale;
                }
            }
        }
    }
    __syncthreads();

    const int c = min(cnt, LIST_CAP);
    const float4* __restrict__ seqb = (const float4*)seq + (long long)b * S * D4;
    float4* __restrict__ outb = (float4*)out + (long long)b * N * D4;

    // ---- serial span loop; rows L1-resident across spans ----
    for (int i = 0; i < c; ++i) {
        const int4 e = list[i];
        const float4* p = seqb + e.y * D4 + t;

        float4 acc = make_float4(0.f, 0.f, 0.f, 0.f);
        #pragma unroll 4
        for (int r = 0; r < e.z; ++r) {
            float4 v = *p;
            p += D4;
            acc.x += v.x; acc.y += v.y; acc.z += v.z; acc.w += v.w;
        }

        const float s = (float)e.w / (float)e.z;
        acc.x *= s; acc.y *= s; acc.z *= s; acc.w *= s;

        outb[e.x * D4 + t] = acc;
    }
}

extern "C" void kernel_launch(void* const* d_in, const int* in_sizes, int n_in,
                              void* d_out, int out_size)
{
    const float* seq  = (const float*)d_in[0];
    const int* spans  = (const int*)d_in[1];
    const int* mask   = (const int*)d_in[2];
    float* out        = (float*)d_out;

    const int S = 2048;
    const int B = in_sizes[0] / (S * DIM);       // 8
    const int N = in_sizes[2] / B;               // 1024

    dim3 grid(S / BW, B);                        // (128, 8) = 1024 CTAs
    avg_span_kernel<<<grid, 128>>>(seq, spans, mask, out, S, N);
}